// round 16
// baseline (speedup 1.0000x reference)
#include <cuda_runtime.h>
#include <stdint.h>

#define BB 128
#define TT 1024
#define DD 256
#define UU 48

// Scratch (allocation-free rule: __device__ globals)
__device__ float         g_logits[(size_t)BB * TT * UU];     // 25.2 MB
__device__ unsigned char g_bp[(size_t)(TT - 1) * BB * UU];   // 6.29 MB
__device__ int           g_last[BB];

#define ADD_F32X2(out, a, b) \
    asm("add.rn.f32x2 %0, %1, %2;" : "=l"(out) : "l"(a), "l"(b))

#define GR 128
#define GK 64
#define XPAD 130
#define NCH 8          // 8 chunks of 128 logits rows per batch

#define BAR_FWD()  asm volatile("bar.sync 1, 96;"  ::: "memory")
#define BAR_GEMM() asm volatile("bar.sync 2, 128;" ::: "memory")

// ---------------------------------------------------------------------------
// Unified (val, argmax-first-index) over 24 candidates [base, base+24).
// Strict-greater replacement, slots ascend with candidate index =>
// first-index tie-break (matches jnp.argmax). Value path = fmaxf.
// (Bitwise-identical to the R15 306us kernel.)
// ---------------------------------------------------------------------------
__device__ __forceinline__ void valIdx24(const unsigned long long (&tr2)[12],
                                         const float* __restrict__ stp,
                                         int base, float& bvo, int& bio) {
    float v[12];
    int   ix[12];
#pragma unroll
    for (int m = 0; m < 6; m++) {
        ulonglong2 s = *(const ulonglong2*)&stp[base + 4 * m];
        unsigned long long ca, cb;
        ADD_F32X2(ca, s.x, tr2[2 * m + 0]);
        ADD_F32X2(cb, s.y, tr2[2 * m + 1]);
        float a0 = __uint_as_float((unsigned)(ca & 0xFFFFFFFFull));
        float a1 = __uint_as_float((unsigned)(ca >> 32));
        float b0 = __uint_as_float((unsigned)(cb & 0xFFFFFFFFull));
        float b1 = __uint_as_float((unsigned)(cb >> 32));
        v[2 * m + 0]  = fmaxf(a0, a1);
        ix[2 * m + 0] = (a1 > a0) ? (4 * m + 1) : (4 * m + 0);
        v[2 * m + 1]  = fmaxf(b0, b1);
        ix[2 * m + 1] = (b1 > b0) ? (4 * m + 3) : (4 * m + 2);
    }
#pragma unroll
    for (int j = 0; j < 6; j++) {
        bool g = v[2 * j + 1] > v[2 * j];
        v[j]  = fmaxf(v[2 * j], v[2 * j + 1]);
        ix[j] = g ? ix[2 * j + 1] : ix[2 * j];
    }
#pragma unroll
    for (int j = 0; j < 3; j++) {
        bool g = v[2 * j + 1] > v[2 * j];
        v[j]  = fmaxf(v[2 * j], v[2 * j + 1]);
        ix[j] = g ? ix[2 * j + 1] : ix[2 * j];
    }
    float m01 = fmaxf(v[0], v[1]);
    int  i01  = (v[1] > v[0]) ? ix[1] : ix[0];
    bvo = fmaxf(m01, v[2]);
    bio = ((v[2] > m01) ? ix[2] : i01) + base;
}

// ---------------------------------------------------------------------------
// Fused kernel: ONE block per batch, 224 threads / 7 warps.
//   warps 0-3 (tid 0-127):   GEMM for this batch (8 chunks x 128 rows),
//     byte-identical tile math to the proven 107us gemm; publishes per-chunk
//     smem flags (threadfence_block + volatile STS).
//   warps 4-6 (tid 128-223): Viterbi forward, R15 96-thread unified layout;
//     gates each logits prefetch LDG on the chunk flag (8 polls / 1023 steps).
// fwd takes the HIGH warp ids: arbiter is hi-wid-first, so the latency-
// critical recurrence wins issue slots over the bandwidth-y gemm warps.
// Named barriers (1:fwd/96, 2:gemm/128) keep roles decoupled.
// ---------------------------------------------------------------------------
__global__ __launch_bounds__(224, 1) void fused_kernel(
        const float* __restrict__ x, const float* __restrict__ w,
        const float* __restrict__ bias, const float* __restrict__ trans) {
    __shared__ float xs[GK][XPAD];              // 33280 B
    __shared__ float ws[GK][UU];                // 12288 B
    __shared__ __align__(16) float st[2][UU];   // 384 B
    __shared__ int sflag[NCH];                  // 32 B

    const int b   = blockIdx.x;
    const int tid = threadIdx.x;

    if (tid < NCH) sflag[tid] = 0;
    __syncthreads();   // only block-wide sync; roles diverge after this

    if (tid < 128) {
        // ===================== GEMM role (warps 0-3) =====================
        const int g  = tid;
        const int tc = g & 3;
        const int tr = g >> 2;

        float bv[12];
#pragma unroll
        for (int j = 0; j < 12; j++) bv[j] = bias[tc * 12 + j];

        for (int c = 0; c < NCH; ++c) {
            const size_t row0 = (size_t)b * TT + (size_t)c * GR;

            float acc[4][12];
#pragma unroll
            for (int i = 0; i < 4; i++)
#pragma unroll
                for (int j = 0; j < 12; j++) acc[i][j] = 0.0f;

            for (int kc = 0; kc < DD; kc += GK) {
                const float4* wg = (const float4*)(w + (size_t)kc * UU);
                float4* wsv = (float4*)&ws[0][0];
#pragma unroll
                for (int i = 0; i < 6; i++) wsv[g + i * 128] = wg[g + i * 128];

#pragma unroll
                for (int i = 0; i < 16; i++) {
                    int j  = g + i * 128;
                    int r  = j >> 4;
                    int k4 = j & 15;
                    float4 f = *(const float4*)(x + (row0 + (size_t)r) * DD + kc + k4 * 4);
                    xs[k4 * 4 + 0][r] = f.x;
                    xs[k4 * 4 + 1][r] = f.y;
                    xs[k4 * 4 + 2][r] = f.z;
                    xs[k4 * 4 + 3][r] = f.w;
                }
                BAR_GEMM();

#pragma unroll 4
                for (int k = 0; k < GK; k++) {
                    float xv[4], wv[12];
                    float2 xa = *(const float2*)&xs[k][tr * 4];
                    float2 xb = *(const float2*)&xs[k][tr * 4 + 2];
                    xv[0] = xa.x; xv[1] = xa.y; xv[2] = xb.x; xv[3] = xb.y;
#pragma unroll
                    for (int q = 0; q < 3; q++) {
                        float4 wq = *(const float4*)&ws[k][tc * 12 + q * 4];
                        wv[q * 4 + 0] = wq.x; wv[q * 4 + 1] = wq.y;
                        wv[q * 4 + 2] = wq.z; wv[q * 4 + 3] = wq.w;
                    }
#pragma unroll
                    for (int i = 0; i < 4; i++)
#pragma unroll
                        for (int j = 0; j < 12; j++) acc[i][j] += xv[i] * wv[j];
                }
                BAR_GEMM();
            }

#pragma unroll
            for (int i = 0; i < 4; i++) {
                size_t r = row0 + tr * 4 + i;
                float* o = g_logits + r * UU + tc * 12;
#pragma unroll
                for (int j = 0; j < 12; j++) o[j] = acc[i][j] + bv[j];
            }
            // publish chunk c: make this thread's STGs CTA-visible, sync
            // gemm warps, then one lane raises the flag.
            __threadfence_block();
            BAR_GEMM();
            if (g == 0) ((volatile int*)sflag)[c] = 1;
        }
        return;
    }

    // ===================== FWD role (warps 4-6) =====================
    const int ft   = tid - 128;       // 0..95
    const int u    = ft >> 1;
    const int h    = ft & 1;
    const int base = 24 * h;

    unsigned long long tr2[12];
#pragma unroll
    for (int j = 0; j < 12; j++) {
        unsigned lo = __float_as_uint(trans[(base + 2 * j) * UU + u]);
        unsigned hi = __float_as_uint(trans[(base + 2 * j + 1) * UU + u]);
        tr2[j] = (unsigned long long)lo | ((unsigned long long)hi << 32);
    }

    const float* lg = g_logits + (size_t)b * TT * UU + u;
    volatile int* vsf = (volatile int*)sflag;
    int conf = 0;

    // wait for chunk 0 (rows 0..127), then init state + prefetch depth 4
    while (vsf[0] == 0) __nanosleep(128);
    __threadfence_block();

    if (h == 0) st[0][u] = lg[0];
    float fb[4];
    fb[0] = lg[(size_t)1 * UU];
    fb[1] = lg[(size_t)2 * UU];
    fb[2] = lg[(size_t)3 * UU];
    fb[3] = lg[(size_t)4 * UU];

    unsigned char* bpb = g_bp + (size_t)b * UU + u;

    BAR_FWD();

    int p = 0;
    int tb = 1;
    for (; tb + 3 < TT; tb += 4) {
#pragma unroll
        for (int q = 0; q < 4; q++) {
            const int t = tb + q;
            float cur = fb[q];
            int tn = t + 4;
            if (tn > TT - 1) tn = TT - 1;
            int need = tn >> 7;                 // chunk of row tn (monotone)
            if (need > conf) {
                while (vsf[need] == 0) __nanosleep(64);
                __threadfence_block();
                conf = need;
            }
            fb[q] = lg[(size_t)tn * UU];        // consumed 4 steps later

            float bv; int bi;
            valIdx24(tr2, st[p], base, bv, bi);

            float ov = __shfl_down_sync(0xFFFFFFFFu, bv, 1);
            int   oi = __shfl_down_sync(0xFFFFFFFFu, bi, 1);
            float mv = fmaxf(bv, ov);           // value: FMNMX on chain
            int   mi = (ov > bv) ? oi : bi;     // index: high half strict >

            if (h == 0) {
                st[p ^ 1][u] = cur + mv;
                bpb[(size_t)(t - 1) * BB * UU] = (unsigned char)mi;
            }
            BAR_FWD();
            p ^= 1;
        }
    }
    // epilogue: t = tb .. TT-1 (3 steps; fb[0..2] already hold their logits)
#pragma unroll
    for (int q = 0; q < 3; q++) {
        const int t = tb + q;
        if (t < TT) {
            float bv; int bi;
            valIdx24(tr2, st[p], base, bv, bi);
            float ov = __shfl_down_sync(0xFFFFFFFFu, bv, 1);
            int   oi = __shfl_down_sync(0xFFFFFFFFu, bi, 1);
            float mv = fmaxf(bv, ov);
            int   mi = (ov > bv) ? oi : bi;
            if (h == 0) {
                st[p ^ 1][u] = fb[q] + mv;
                bpb[(size_t)(t - 1) * BB * UU] = (unsigned char)mi;
            }
            BAR_FWD();
            p ^= 1;
        }
    }

    if (ft == 0) {
        float bv = st[p][0];
        int bi = 0;
#pragma unroll
        for (int i = 1; i < UU; i++) {
            if (st[p][i] > bv) { bv = st[p][i]; bi = i; }
        }
        g_last[b] = bi;
    }
}

// ---------------------------------------------------------------------------
// Kernel 2: backtrack + emit (measured 29.5us). 128 blocks, 256 threads.
// Stage bp column to SMEM, branchless LDS.U8 chain walk, float output.
// ---------------------------------------------------------------------------
__global__ __launch_bounds__(256) void backtrack_kernel(float* __restrict__ out) {
    __shared__ unsigned char sbp[(TT - 1) * UU];  // 49104 B

    const int b = blockIdx.x;
    const int tid = threadIdx.x;

    const unsigned char* gsrc = g_bp + (size_t)b * UU;
    for (int idx = tid; idx < (TT - 1) * 3; idx += 256) {
        int s = idx / 3;
        int w = idx % 3;
        uint4 v = *(const uint4*)(gsrc + (size_t)s * BB * UU + w * 16);
        *(uint4*)(sbp + s * UU + w * 16) = v;
    }
    __syncthreads();

    if (tid != 0) return;

    int tag = g_last[b];
    float* ob = out + (size_t)b * TT;
    ob[TT - 1] = (float)tag;

    int off = (TT - 2) * UU;
#pragma unroll 8
    for (int s = TT - 2; s >= 0; --s) {
        tag = sbp[off + tag];
        ob[s] = (float)tag;
        off -= UU;
    }
}

// ---------------------------------------------------------------------------
extern "C" void kernel_launch(void* const* d_in, const int* in_sizes, int n_in,
                              void* d_out, int out_size) {
    const float* x     = (const float*)d_in[0];  // (128,1024,256)
    const float* kern  = (const float*)d_in[1];  // (256,48)
    const float* bias  = (const float*)d_in[2];  // (48,)
    const float* chain = (const float*)d_in[3];  // (48,48)
    float* out = (float*)d_out;                  // (128,1024) float32

    fused_kernel<<<BB, 224>>>(x, kern, bias, chain);
    backtrack_kernel<<<BB, 256>>>(out);
}

// round 17
// speedup vs baseline: 1.2056x; 1.2056x over previous
#include <cuda_runtime.h>
#include <stdint.h>

#define BB 128
#define TT 1024
#define DD 256
#define UU 48

__device__ int g_last_unused[1];  // (bp/tags now live in smem; no gmem scratch)

#define ADD_F32X2(out, a, b) \
    asm("add.rn.f32x2 %0, %1, %2;" : "=l"(out) : "l"(a), "l"(b))

#define BAR_FWD() asm volatile("bar.sync 1, 96;" ::: "memory")

// ---------------------------------------------------------------------------
// Kernel 1: logits = x @ kernel + bias.
// XPAD 132 (16B-aligned row stride): row operands load as 1 LDS.128 instead
// of 2 LDS.64 -> 4 LDS per k for 48 FFMA (ncu: L1 70% was the binding pipe).
// Math bitwise-identical (same values, same k order).
// ---------------------------------------------------------------------------
#define GR 128
#define GK 64
#define XPAD 132

__device__ float g_logits[(size_t)BB * TT * UU];   // 25.2 MB

__global__ __launch_bounds__(128) void gemm_kernel(const float* __restrict__ x,
                                                   const float* __restrict__ w,
                                                   const float* __restrict__ bias) {
    __shared__ float xs[GK][XPAD];
    __shared__ float ws[GK][UU];

    const int tid = threadIdx.x;
    const int tc  = tid & 3;
    const int tr  = tid >> 2;
    const size_t row0 = (size_t)blockIdx.x * GR;

    float acc[4][12];
#pragma unroll
    for (int i = 0; i < 4; i++)
#pragma unroll
        for (int j = 0; j < 12; j++) acc[i][j] = 0.0f;

    for (int kc = 0; kc < DD; kc += GK) {
        const float4* wg = (const float4*)(w + (size_t)kc * UU);
        float4* wsv = (float4*)&ws[0][0];
#pragma unroll
        for (int i = 0; i < 6; i++) wsv[tid + i * 128] = wg[tid + i * 128];

#pragma unroll
        for (int i = 0; i < 16; i++) {
            int j  = tid + i * 128;
            int r  = j >> 4;
            int k4 = j & 15;
            float4 f = *(const float4*)(x + (row0 + (size_t)r) * DD + kc + k4 * 4);
            xs[k4 * 4 + 0][r] = f.x;
            xs[k4 * 4 + 1][r] = f.y;
            xs[k4 * 4 + 2][r] = f.z;
            xs[k4 * 4 + 3][r] = f.w;
        }
        __syncthreads();

#pragma unroll 4
        for (int k = 0; k < GK; k++) {
            float xv[4], wv[12];
            float4 xq = *(const float4*)&xs[k][tr * 4];   // 16B-aligned now
            xv[0] = xq.x; xv[1] = xq.y; xv[2] = xq.z; xv[3] = xq.w;
#pragma unroll
            for (int q = 0; q < 3; q++) {
                float4 wq = *(const float4*)&ws[k][tc * 12 + q * 4];
                wv[q * 4 + 0] = wq.x; wv[q * 4 + 1] = wq.y;
                wv[q * 4 + 2] = wq.z; wv[q * 4 + 3] = wq.w;
            }
#pragma unroll
            for (int i = 0; i < 4; i++)
#pragma unroll
                for (int j = 0; j < 12; j++) acc[i][j] += xv[i] * wv[j];
        }
        __syncthreads();
    }

    float bv[12];
#pragma unroll
    for (int j = 0; j < 12; j++) bv[j] = bias[tc * 12 + j];

#pragma unroll
    for (int i = 0; i < 4; i++) {
        size_t r = row0 + tr * 4 + i;
        float* o = g_logits + r * UU + tc * 12;
#pragma unroll
        for (int j = 0; j < 12; j++) o[j] = acc[i][j] + bv[j];
    }
}

// ---------------------------------------------------------------------------
// Unified (val, argmax-first-index) over 24 candidates [base, base+24).
// Strict-greater replacement, slots ascend with candidate index =>
// first-index tie-break (matches jnp.argmax). Bitwise-identical to R15.
// ---------------------------------------------------------------------------
__device__ __forceinline__ void valIdx24(const unsigned long long (&tr2)[12],
                                         const float* __restrict__ stp,
                                         int base, float& bvo, int& bio) {
    float v[12];
    int   ix[12];
#pragma unroll
    for (int m = 0; m < 6; m++) {
        ulonglong2 s = *(const ulonglong2*)&stp[base + 4 * m];
        unsigned long long ca, cb;
        ADD_F32X2(ca, s.x, tr2[2 * m + 0]);
        ADD_F32X2(cb, s.y, tr2[2 * m + 1]);
        float a0 = __uint_as_float((unsigned)(ca & 0xFFFFFFFFull));
        float a1 = __uint_as_float((unsigned)(ca >> 32));
        float b0 = __uint_as_float((unsigned)(cb & 0xFFFFFFFFull));
        float b1 = __uint_as_float((unsigned)(cb >> 32));
        v[2 * m + 0]  = fmaxf(a0, a1);
        ix[2 * m + 0] = (a1 > a0) ? (4 * m + 1) : (4 * m + 0);
        v[2 * m + 1]  = fmaxf(b0, b1);
        ix[2 * m + 1] = (b1 > b0) ? (4 * m + 3) : (4 * m + 2);
    }
#pragma unroll
    for (int j = 0; j < 6; j++) {
        bool g = v[2 * j + 1] > v[2 * j];
        v[j]  = fmaxf(v[2 * j], v[2 * j + 1]);
        ix[j] = g ? ix[2 * j + 1] : ix[2 * j];
    }
#pragma unroll
    for (int j = 0; j < 3; j++) {
        bool g = v[2 * j + 1] > v[2 * j];
        v[j]  = fmaxf(v[2 * j], v[2 * j + 1]);
        ix[j] = g ? ix[2 * j + 1] : ix[2 * j];
    }
    float m01 = fmaxf(v[0], v[1]);
    int  i01  = (v[1] > v[0]) ? ix[1] : ix[0];
    bvo = fmaxf(m01, v[2]);
    bio = ((v[2] > m01) ? ix[2] : i01) + base;
}

// ---------------------------------------------------------------------------
// Kernel 2: Viterbi forward + backtrack + emit, fused. One block per batch,
// 96 threads / 3 warps (R15 unified layout, bitwise-identical recurrence).
// Backpointers go to SMEM (1023 x 48 B = 49104 B, dynamic) instead of gmem;
// after the final step, thread 0 walks the chain in-place (branchless
// LDS.U8) and writes the float output row directly. Deletes the 29.5us
// backtrack kernel and all bp DRAM traffic.
// ---------------------------------------------------------------------------
#define SBP_BYTES ((TT - 1) * UU)                   // 49104
#define FWD_SMEM  (SBP_BYTES + 2 * UU * 4)          // + st[2][48] = 49488

__global__ __launch_bounds__(96) void viterbi_fwd(const float* __restrict__ trans,
                                                  float* __restrict__ out) {
    extern __shared__ __align__(16) unsigned char dyn[];
    unsigned char* sbp = dyn;                        // [t-1][u] bytes
    float* st = (float*)(dyn + SBP_BYTES);           // st[2][UU] (16B-aligned)

    const int b    = blockIdx.x;
    const int tid  = threadIdx.x;
    const int u    = tid >> 1;
    const int h    = tid & 1;
    const int base = 24 * h;

    unsigned long long tr2[12];
#pragma unroll
    for (int j = 0; j < 12; j++) {
        unsigned lo = __float_as_uint(trans[(base + 2 * j) * UU + u]);
        unsigned hi = __float_as_uint(trans[(base + 2 * j + 1) * UU + u]);
        tr2[j] = (unsigned long long)lo | ((unsigned long long)hi << 32);
    }

    const float* lg = g_logits + (size_t)b * TT * UU + u;
    if (h == 0) st[u] = lg[0];

    float fb[4];
    fb[0] = lg[(size_t)1 * UU];
    fb[1] = lg[(size_t)2 * UU];
    fb[2] = lg[(size_t)3 * UU];
    fb[3] = lg[(size_t)4 * UU];

    BAR_FWD();

    int p = 0;
    int tb = 1;
    for (; tb + 3 < TT; tb += 4) {
#pragma unroll
        for (int q = 0; q < 4; q++) {
            const int t = tb + q;
            float cur = fb[q];
            int tn = t + 4;
            if (tn > TT - 1) tn = TT - 1;
            fb[q] = lg[(size_t)tn * UU];        // consumed 4 steps later

            float bv; int bi;
            valIdx24(tr2, st + p * UU, base, bv, bi);

            float ov = __shfl_down_sync(0xFFFFFFFFu, bv, 1);
            int   oi = __shfl_down_sync(0xFFFFFFFFu, bi, 1);
            float mv = fmaxf(bv, ov);           // value: FMNMX on chain
            int   mi = (ov > bv) ? oi : bi;     // index: high half strict >

            if (h == 0) {
                st[(p ^ 1) * UU + u] = cur + mv;
                sbp[(t - 1) * UU + u] = (unsigned char)mi;
            }
            BAR_FWD();
            p ^= 1;
        }
    }
    // epilogue: t = tb .. TT-1 (3 steps; fb[0..2] already hold their logits)
#pragma unroll
    for (int q = 0; q < 3; q++) {
        const int t = tb + q;
        if (t < TT) {
            float bv; int bi;
            valIdx24(tr2, st + p * UU, base, bv, bi);
            float ov = __shfl_down_sync(0xFFFFFFFFu, bv, 1);
            int   oi = __shfl_down_sync(0xFFFFFFFFu, bi, 1);
            float mv = fmaxf(bv, ov);
            int   mi = (ov > bv) ? oi : bi;
            if (h == 0) {
                st[(p ^ 1) * UU + u] = fb[q] + mv;
                sbp[(t - 1) * UU + u] = (unsigned char)mi;
            }
            BAR_FWD();
            p ^= 1;
        }
    }

    // ---- backtrack + emit tail (thread 0; sbp fully drained by last BAR) ----
    if (tid == 0) {
        const float* stf = st + p * UU;
        float bv = stf[0];
        int tag = 0;
#pragma unroll
        for (int i = 1; i < UU; i++) {
            if (stf[i] > bv) { bv = stf[i]; tag = i; }
        }
        float* ob = out + (size_t)b * TT;
        ob[TT - 1] = (float)tag;

        int off = (TT - 2) * UU;
#pragma unroll 8
        for (int s = TT - 2; s >= 0; --s) {
            tag = sbp[off + tag];
            ob[s] = (float)tag;
            off -= UU;
        }
    }
}

// ---------------------------------------------------------------------------
extern "C" void kernel_launch(void* const* d_in, const int* in_sizes, int n_in,
                              void* d_out, int out_size) {
    const float* x     = (const float*)d_in[0];  // (128,1024,256)
    const float* kern  = (const float*)d_in[1];  // (256,48)
    const float* bias  = (const float*)d_in[2];  // (48,)
    const float* chain = (const float*)d_in[3];  // (48,48)
    float* out = (float*)d_out;                  // (128,1024) float32

    // >48KB dynamic smem opt-in (host attribute set; not a stream op, so
    // graph-capture-safe; idempotent across calls).
    cudaFuncSetAttribute(viterbi_fwd,
                         cudaFuncAttributeMaxDynamicSharedMemorySize, FWD_SMEM);

    gemm_kernel<<<(BB * TT) / GR, 128>>>(x, kern, bias);
    viterbi_fwd<<<BB, 96, FWD_SMEM>>>(chain, out);
}